// round 11
// baseline (speedup 1.0000x reference)
#include <cuda_runtime.h>
#include <cuda_bf16.h>
#include <math.h>
#include <cstdint>

#define HEADS    16
#define HEAD_DIM 128
#define B_       2
#define T_       2048
#define DIM      2048
#define INNER    (HEADS * HEAD_DIM)   // 2048
#define QKV_N    (3 * INNER)          // 6144
#define MTOK     (B_ * T_)            // 4096

// ---------------------------------------------------------------------------
// Scratch (allocation-free rule: __device__ globals)
// ---------------------------------------------------------------------------
__device__ __nv_bfloat16 g_qkvh[(size_t)MTOK * QKV_N], g_qkvl[(size_t)MTOK * QKV_N];
__device__ __nv_bfloat16 g_xh[(size_t)MTOK * DIM],  g_xl[(size_t)MTOK * DIM];
__device__ __nv_bfloat16 g_wqh[(size_t)QKV_N * DIM], g_wql[(size_t)QKV_N * DIM];
__device__ __nv_bfloat16 g_wph[(size_t)INNER * DIM], g_wpl[(size_t)INNER * DIM];
__device__ __nv_bfloat16 g_ah[(size_t)MTOK * INNER], g_al[(size_t)MTOK * INNER];
__device__ float2 g_rope[(size_t)T_ * 64];           // cos/sin table

// ---------------------------------------------------------------------------
// PTX helpers (baseline ISA only — plain sm_103 target)
// ---------------------------------------------------------------------------
__device__ __forceinline__ uint32_t smem_to_u32(const void* p) {
    uint32_t a;
    asm("{ .reg .u64 t; cvta.to.shared.u64 t, %1; cvt.u32.u64 %0, t; }"
        : "=r"(a) : "l"(p));
    return a;
}
__device__ __forceinline__ void cp_async16(uint32_t dst, const void* src) {
    asm volatile("cp.async.cg.shared.global [%0], [%1], 16;" :: "r"(dst), "l"(src));
}
#define CP_COMMIT() asm volatile("cp.async.commit_group;" ::: "memory")
#define CP_WAIT(n)  asm volatile("cp.async.wait_group %0;" :: "n"(n) : "memory")

#define LDSM_X4(r0, r1, r2, r3, addr) \
    asm volatile("ldmatrix.sync.aligned.m8n8.x4.shared.b16 {%0,%1,%2,%3}, [%4];" \
        : "=r"(r0), "=r"(r1), "=r"(r2), "=r"(r3) : "r"(addr))
#define LDSM_X4_T(r0, r1, r2, r3, addr) \
    asm volatile("ldmatrix.sync.aligned.m8n8.x4.trans.shared.b16 {%0,%1,%2,%3}, [%4];" \
        : "=r"(r0), "=r"(r1), "=r"(r2), "=r"(r3) : "r"(addr))

__device__ __forceinline__ void mma_bf16(float* c, const uint32_t* a, const uint32_t* b)
{
    asm volatile(
        "mma.sync.aligned.m16n8k16.row.col.f32.bf16.bf16.f32 "
        "{%0,%1,%2,%3}, {%4,%5,%6,%7}, {%8,%9}, {%0,%1,%2,%3};"
        : "+f"(c[0]), "+f"(c[1]), "+f"(c[2]), "+f"(c[3])
        : "r"(a[0]), "r"(a[1]), "r"(a[2]), "r"(a[3]), "r"(b[0]), "r"(b[1]));
}

__device__ __forceinline__ uint32_t pack2(__nv_bfloat16 a, __nv_bfloat16 b) {
    __nv_bfloat162 t(a, b);
    return *reinterpret_cast<uint32_t*>(&t);
}
__device__ __forceinline__ uint32_t packf2(float lo, float hi) {
    __nv_bfloat162 t = __floats2bfloat162_rn(lo, hi);
    return *reinterpret_cast<uint32_t*>(&t);
}

// ---------------------------------------------------------------------------
// Split fp32 -> (hi bf16, lo bf16)
// ---------------------------------------------------------------------------
__global__ void split_kernel(const float* __restrict__ src,
                             __nv_bfloat16* __restrict__ hi,
                             __nv_bfloat16* __restrict__ lo, int n4)
{
    int i = blockIdx.x * 256 + threadIdx.x;
    if (i >= n4) return;
    float4 v = ((const float4*)src)[i];
    float f[4] = {v.x, v.y, v.z, v.w};
    __nv_bfloat162 h2[2], l2[2];
#pragma unroll
    for (int j = 0; j < 2; j++) {
        __nv_bfloat16 h0 = __float2bfloat16(f[2 * j]);
        __nv_bfloat16 h1 = __float2bfloat16(f[2 * j + 1]);
        __nv_bfloat16 l0 = __float2bfloat16(f[2 * j] - __bfloat162float(h0));
        __nv_bfloat16 l1 = __float2bfloat16(f[2 * j + 1] - __bfloat162float(h1));
        h2[j] = __nv_bfloat162(h0, h1);
        l2[j] = __nv_bfloat162(l0, l1);
    }
    ((__nv_bfloat162*)hi)[2 * i]     = h2[0];
    ((__nv_bfloat162*)hi)[2 * i + 1] = h2[1];
    ((__nv_bfloat162*)lo)[2 * i]     = l2[0];
    ((__nv_bfloat162*)lo)[2 * i + 1] = l2[1];
}

// ---------------------------------------------------------------------------
// RoPE cos/sin table init
// ---------------------------------------------------------------------------
__global__ void rope_table_kernel(float2* __restrict__ tab)
{
    int idx = blockIdx.x * 256 + threadIdx.x;   // 0 .. 2048*64-1
    int i = idx & 63;
    int t = idx >> 6;
    float inv = exp2f(-(float)i * 0.20761871929656223f);  // log2(1e4)/64
    float ang = (float)t * inv;
    float sn, cs;
    sincosf(ang, &sn, &cs);
    tab[idx] = make_float2(cs, sn);
}

// ---------------------------------------------------------------------------
// HMMA GEMM (v4 core, unchanged from round 10): 3-term bf16 split.
// Tile 128x128, BK=32, 8 warps (2x4), warp tile 64x32, 2-stage cp.async,
// 2 CTAs/SM, mi pairs (8 indep chains).
// mode 0: fp32 C.  mode 1: fused RoPE + hi/lo split epilogue (vectorized).
// ---------------------------------------------------------------------------
#define GBM 128
#define GBN 128
#define GBK 32
#define LDA 40
#define MAT_BYTES (128 * LDA * 2)           // 10240
#define STAGE_BYTES (4 * MAT_BYTES)         // 40960
#define GEMM_SMEM (2 * STAGE_BYTES)         // 81920 per CTA -> 2 CTAs/SM
#define LDC 132                             // fp32 epilogue staging stride

__device__ __forceinline__ void issue_stage(
    const __nv_bfloat16* __restrict__ Ah, const __nv_bfloat16* __restrict__ Al,
    const __nv_bfloat16* __restrict__ Bh, const __nv_bfloat16* __restrict__ Bl,
    size_t bm, size_t bn, int K, int k0, uint32_t sbase, int tid)
{
#pragma unroll
    for (int i = 0; i < 2; i++) {
        int idx = tid + i * 256;            // 0..511
        int r   = idx >> 2;                 // 0..127
        int c   = (idx & 3) << 3;           // 0,8,16,24
        uint32_t doff = (uint32_t)(r * LDA + c) * 2;
        size_t asrc = (bm + (size_t)r) * K + k0 + c;
        size_t bsrc = (bn + (size_t)r) * K + k0 + c;
        cp_async16(sbase + doff,                 Ah + asrc);
        cp_async16(sbase + MAT_BYTES + doff,     Al + asrc);
        cp_async16(sbase + 2 * MAT_BYTES + doff, Bh + bsrc);
        cp_async16(sbase + 3 * MAT_BYTES + doff, Bl + bsrc);
    }
}

__global__ __launch_bounds__(256, 2)
void gemm_bf16x3(const __nv_bfloat16* __restrict__ Ah, const __nv_bfloat16* __restrict__ Al,
                 const __nv_bfloat16* __restrict__ Bh, const __nv_bfloat16* __restrict__ Bl,
                 float* __restrict__ C,
                 __nv_bfloat16* __restrict__ Oh, __nv_bfloat16* __restrict__ Ol,
                 const float2* __restrict__ rope,
                 int M, int N, int K, int mode)
{
    extern __shared__ char smem[];
    const uint32_t s0 = smem_to_u32(smem);

    const int tid = threadIdx.x;
    const int wid = tid >> 5;
    const int l   = tid & 31;
    const int warp_m = wid & 1;
    const int warp_n = wid >> 1;
    const size_t bm = (size_t)blockIdx.y * GBM;
    const size_t bn = (size_t)blockIdx.x * GBN;

    float acc[4][4][4];
#pragma unroll
    for (int mi = 0; mi < 4; mi++)
#pragma unroll
        for (int ni = 0; ni < 4; ni++)
#pragma unroll
            for (int e = 0; e < 4; e++) acc[mi][ni][e] = 0.f;

    const int S = K / GBK;
    issue_stage(Ah, Al, Bh, Bl, bm, bn, K, 0, s0, tid);
    CP_COMMIT();

    const int a_row = warp_m * 64 + (l & 15);
    const int a_ch  = (l >> 4) << 3;
    const int g     = l >> 3;
    const int b_row = warp_n * 32 + ((g >> 1) << 3) + (l & 7);
    const int b_ch  = (g & 1) << 3;

    for (int s = 0; s < S; s++) {
        if (s + 1 < S) {
            issue_stage(Ah, Al, Bh, Bl, bm, bn, K, (s + 1) * GBK,
                        s0 + ((s + 1) & 1) * STAGE_BYTES, tid);
            CP_COMMIT();
            CP_WAIT(1);
        } else {
            CP_WAIT(0);
        }
        __syncthreads();

        const uint32_t ahB = s0 + (s & 1) * STAGE_BYTES;
        const uint32_t alB = ahB + MAT_BYTES;
        const uint32_t bhB = ahB + 2 * MAT_BYTES;
        const uint32_t blB = ahB + 3 * MAT_BYTES;

#pragma unroll
        for (int ks = 0; ks < 2; ks++) {
            const int kc = ks * 16;
            uint32_t bh[4][2], bl[4][2];
#pragma unroll
            for (int nt = 0; nt < 2; nt++) {
                uint32_t off = (uint32_t)((b_row + nt * 16) * LDA + kc + b_ch) * 2;
                LDSM_X4(bh[2 * nt][0], bh[2 * nt][1], bh[2 * nt + 1][0], bh[2 * nt + 1][1], bhB + off);
                LDSM_X4(bl[2 * nt][0], bl[2 * nt][1], bl[2 * nt + 1][0], bl[2 * nt + 1][1], blB + off);
            }
#pragma unroll
            for (int mp = 0; mp < 2; mp++) {
                const int mi0 = 2 * mp, mi1 = 2 * mp + 1;
                uint32_t ah0[4], al0[4], ah1[4], al1[4];
                uint32_t off0 = (uint32_t)((a_row + mi0 * 16) * LDA + kc + a_ch) * 2;
                uint32_t off1 = (uint32_t)((a_row + mi1 * 16) * LDA + kc + a_ch) * 2;
                LDSM_X4(ah0[0], ah0[1], ah0[2], ah0[3], ahB + off0);
                LDSM_X4(ah1[0], ah1[1], ah1[2], ah1[3], ahB + off1);
                LDSM_X4(al0[0], al0[1], al0[2], al0[3], alB + off0);
                LDSM_X4(al1[0], al1[1], al1[2], al1[3], alB + off1);
#pragma unroll
                for (int ni = 0; ni < 4; ni++) {
                    mma_bf16(acc[mi0][ni], ah0, bh[ni]);
                    mma_bf16(acc[mi1][ni], ah1, bh[ni]);
                }
#pragma unroll
                for (int ni = 0; ni < 4; ni++) {
                    mma_bf16(acc[mi0][ni], al0, bh[ni]);
                    mma_bf16(acc[mi1][ni], al1, bh[ni]);
                }
#pragma unroll
                for (int ni = 0; ni < 4; ni++) {
                    mma_bf16(acc[mi0][ni], ah0, bl[ni]);
                    mma_bf16(acc[mi1][ni], ah1, bl[ni]);
                }
            }
        }
        __syncthreads();
    }

    if (mode == 0) {
        const size_t row0 = bm + warp_m * 64 + (l >> 2);
        const int    col0 = (int)bn + warp_n * 32 + 2 * (l & 3);
#pragma unroll
        for (int mi = 0; mi < 4; mi++) {
#pragma unroll
            for (int ni = 0; ni < 4; ni++) {
                float* p0 = C + (row0 + mi * 16) * N + col0 + ni * 8;
                float* p1 = p0 + 8 * (size_t)N;
                *(float2*)p0 = make_float2(acc[mi][ni][0], acc[mi][ni][1]);
                *(float2*)p1 = make_float2(acc[mi][ni][2], acc[mi][ni][3]);
            }
        }
    } else {
        // fused RoPE + hi/lo split epilogue; tile = one head.
        float* sC = (float*)smem;           // 128 x LDC fp32
        const int r0 = warp_m * 64 + (l >> 2);
        const int c0 = warp_n * 32 + 2 * (l & 3);
#pragma unroll
        for (int mi = 0; mi < 4; mi++) {
#pragma unroll
            for (int ni = 0; ni < 4; ni++) {
                int rr = r0 + mi * 16, cc = c0 + ni * 8;
                sC[rr * LDC + cc]           = acc[mi][ni][0];
                sC[rr * LDC + cc + 1]       = acc[mi][ni][1];
                sC[(rr + 8) * LDC + cc]     = acc[mi][ni][2];
                sC[(rr + 8) * LDC + cc + 1] = acc[mi][ni][3];
            }
        }
        __syncthreads();

        const int sec = (int)(bn / INNER);  // 0=q, 1=k, 2=v
#pragma unroll
        for (int j = 0; j < 16; j++) {
            int p = tid + j * 256;          // 0..4095 double-pairs
            int r = p >> 5;                 // 0..127
            int c = (p & 31) << 1;          // 0,2,...,62
            float x1a = sC[r * LDC + c];
            float x1b = sC[r * LDC + c + 1];
            float x2a = sC[r * LDC + c + 64];
            float x2b = sC[r * LDC + c + 65];
            float y1a = x1a, y1b = x1b, y2a = x2a, y2b = x2b;
            if (sec < 2) {
                int t = (int)((bm + r) & (T_ - 1));
                float2 ca = rope[t * 64 + c];
                float2 cb = rope[t * 64 + c + 1];
                y1a = x1a * ca.x - x2a * ca.y;
                y2a = x2a * ca.x + x1a * ca.y;
                y1b = x1b * cb.x - x2b * cb.y;
                y2b = x2b * cb.x + x1b * cb.y;
            }
            __nv_bfloat16 h1a = __float2bfloat16(y1a), h1b = __float2bfloat16(y1b);
            __nv_bfloat16 h2a = __float2bfloat16(y2a), h2b = __float2bfloat16(y2b);
            size_t o = (bm + r) * (size_t)QKV_N + bn + c;
            *(uint32_t*)(Oh + o)      = pack2(h1a, h1b);
            *(uint32_t*)(Oh + o + 64) = pack2(h2a, h2b);
            *(uint32_t*)(Ol + o)      = packf2(y1a - __bfloat162float(h1a),
                                               y1b - __bfloat162float(h1b));
            *(uint32_t*)(Ol + o + 64) = packf2(y2a - __bfloat162float(h2a),
                                               y2b - __bfloat162float(h2b));
        }
    }
}

// ---------------------------------------------------------------------------
// HMMA causal flash attention v2: warp = 32 q-rows, CTA = 256 q-rows (8 warps),
// KV tile = 32 (double-buffered), Q streamed from smem.
// K/V fragment traffic amortized over 2x q-rows -> crossbar cap 66% -> 92%.
// ---------------------------------------------------------------------------
#define ALD 136
#define AQ_BYTES   (256 * ALD * 2)     // 69632 per Q matrix
#define AKV_BYTES  (32 * ALD * 2)      // 8704 per KV matrix
#define AKV_STAGE  (4 * AKV_BYTES)     // 34816
#define ATTN_SMEM  (2 * AQ_BYTES + 2 * AKV_STAGE)   // 208896

__global__ __launch_bounds__(256, 1)
void attn_mma(const __nv_bfloat16* __restrict__ QKVh,
              const __nv_bfloat16* __restrict__ QKVl,
              __nv_bfloat16* __restrict__ outh,
              __nv_bfloat16* __restrict__ outl)
{
    extern __shared__ char smem[];
    const uint32_t s0  = smem_to_u32(smem);
    const uint32_t qhB = s0;
    const uint32_t qlB = s0 + AQ_BYTES;
    const uint32_t kvB = s0 + 2 * AQ_BYTES;

    const int tid = threadIdx.x;
    const int wid = tid >> 5;
    const int l   = tid & 31;
    const int qb  = (int)gridDim.x - 1 - (int)blockIdx.x;   // big tiles first
    const int b   = (int)blockIdx.y >> 4;
    const int h   = (int)blockIdx.y & 15;
    const int q0  = qb * 256;
    const size_t rowbase = (size_t)b * T_;
    const float scale = 0.08838834764831843f;

    // ---- Q prologue: 2 mats x 256 rows x 16 chunks = 8192 cp16 ----
#pragma unroll
    for (int it = 0; it < 32; it++) {
        int idx = tid + it * 256;
        int mat = idx >> 12;
        int r   = (idx >> 4) & 255;
        int c   = idx & 15;
        const __nv_bfloat16* src = (mat ? QKVl : QKVh) +
            (rowbase + q0 + r) * QKV_N + h * HEAD_DIM + c * 8;
        cp_async16((mat ? qlB : qhB) + (uint32_t)(r * ALD + c * 8) * 2, src);
    }

    // ---- KV stage issue: 4 mats x 32 rows x 16 chunks = 2048 cp16 ----
    auto issue_kv = [&](int kv0, int buf) {
        uint32_t base = kvB + (uint32_t)buf * AKV_STAGE;
#pragma unroll
        for (int it = 0; it < 8; it++) {
            int idx = tid + it * 256;
            int m   = idx >> 9;            // 0=Kh 1=Kl 2=Vh 3=Vl
            int r   = (idx >> 4) & 31;
            int c   = idx & 15;
            const __nv_bfloat16* p = (m & 1) ? QKVl : QKVh;
            int sect = (m >> 1) ? 2 * INNER : INNER;
            const __nv_bfloat16* src = p +
                (rowbase + kv0 + r) * QKV_N + sect + h * HEAD_DIM + c * 8;
            cp_async16(base + (uint32_t)m * AKV_BYTES + (uint32_t)(r * ALD + c * 8) * 2, src);
        }
    };

    // lane mappings
    const int a_rowl  = l & 15;            // within 16-row mi tile
    const int a_ch    = (l >> 4) << 3;
    const int g       = l >> 3;
    const int bn_row  = ((g >> 1) << 3) + (l & 7);   // 0..15
    const int b_ch    = (g & 1) << 3;
    const int v_kr    = (((l >> 3) & 1) << 3) + (l & 7);
    const int v_nc    = (l >> 4) << 3;

    float o[2][16][4];
#pragma unroll
    for (int mi = 0; mi < 2; mi++)
#pragma unroll
        for (int n = 0; n < 16; n++)
#pragma unroll
            for (int e = 0; e < 4; e++) o[mi][n][e] = 0.f;
    float mA[2] = {-INFINITY, -INFINITY}, mB[2] = {-INFINITY, -INFINITY};
    float lA[2] = {0.f, 0.f}, lB[2] = {0.f, 0.f};

    const int ntiles = 8 * qb + 8;
    issue_kv(0, 0);
    CP_COMMIT();

    const int row0 = q0 + wid * 32;
    const int r0l  = l >> 2;

    for (int t = 0; t < ntiles; t++) {
        if (t + 1 < ntiles) {
            issue_kv((t + 1) * 32, (t + 1) & 1);
            CP_COMMIT();
            CP_WAIT(1);
        } else {
            CP_WAIT(0);
        }
        __syncthreads();

        const int kv0 = t * 32;
        const uint32_t st = kvB + (uint32_t)(t & 1) * AKV_STAGE;

        if (kv0 <= row0 + 31) {                    // warp has unmasked rows
            // ---- S = Q K^T (3-term split), 2 mi tiles x 32 kv ----
            float s[2][4][4];
#pragma unroll
            for (int mi = 0; mi < 2; mi++)
#pragma unroll
                for (int n = 0; n < 4; n++)
#pragma unroll
                    for (int e = 0; e < 4; e++) s[mi][n][e] = 0.f;

#pragma unroll
            for (int kk = 0; kk < 8; kk++) {
                const int kc = kk * 16;
                uint32_t qh[2][4], ql_[2][4], kh[4][2], kl[4][2];
#pragma unroll
                for (int mi = 0; mi < 2; mi++) {
                    uint32_t qoff = (uint32_t)((wid * 32 + mi * 16 + a_rowl) * ALD + kc + a_ch) * 2;
                    LDSM_X4(qh[mi][0], qh[mi][1], qh[mi][2], qh[mi][3], qhB + qoff);
                    LDSM_X4(ql_[mi][0], ql_[mi][1], ql_[mi][2], ql_[mi][3], qlB + qoff);
                }
#pragma unroll
                for (int nt = 0; nt < 2; nt++) {
                    uint32_t koff = (uint32_t)((nt * 16 + bn_row) * ALD + kc + b_ch) * 2;
                    LDSM_X4(kh[2 * nt][0], kh[2 * nt][1], kh[2 * nt + 1][0], kh[2 * nt + 1][1],
                            st + koff);
                    LDSM_X4(kl[2 * nt][0], kl[2 * nt][1], kl[2 * nt + 1][0], kl[2 * nt + 1][1],
                            st + AKV_BYTES + koff);
                }
#pragma unroll
                for (int mi = 0; mi < 2; mi++)
#pragma unroll
                    for (int n = 0; n < 4; n++) {
                        mma_bf16(s[mi][n], qh[mi],  kh[n]);
                        mma_bf16(s[mi][n], ql_[mi], kh[n]);
                        mma_bf16(s[mi][n], qh[mi],  kl[n]);
                    }
            }

            // ---- scale + causal mask ----
#pragma unroll
            for (int mi = 0; mi < 2; mi++)
#pragma unroll
                for (int n = 0; n < 4; n++)
#pragma unroll
                    for (int e = 0; e < 4; e++) s[mi][n][e] *= scale;

            if (kv0 + 31 > row0) {
                const int cb = kv0 + 2 * (l & 3);
#pragma unroll
                for (int mi = 0; mi < 2; mi++) {
                    const int rA = row0 + mi * 16 + r0l;
                    const int rB = rA + 8;
#pragma unroll
                    for (int n = 0; n < 4; n++) {
                        int c0 = cb + 8 * n;
                        if (c0     > rA) s[mi][n][0] = -INFINITY;
                        if (c0 + 1 > rA) s[mi][n][1] = -INFINITY;
                        if (c0     > rB) s[mi][n][2] = -INFINITY;
                        if (c0 + 1 > rB) s[mi][n][3] = -INFINITY;
                    }
                }
            }

            // ---- online softmax + P fragments + PV ----
            uint32_t ph[2][2][4], pl[2][2][4];
#pragma unroll
            for (int mi = 0; mi < 2; mi++) {
                float mxA = -INFINITY, mxB = -INFINITY;
#pragma unroll
                for (int n = 0; n < 4; n++) {
                    mxA = fmaxf(mxA, fmaxf(s[mi][n][0], s[mi][n][1]));
                    mxB = fmaxf(mxB, fmaxf(s[mi][n][2], s[mi][n][3]));
                }
#pragma unroll
                for (int off = 1; off < 4; off <<= 1) {
                    mxA = fmaxf(mxA, __shfl_xor_sync(0xffffffffu, mxA, off));
                    mxB = fmaxf(mxB, __shfl_xor_sync(0xffffffffu, mxB, off));
                }
                float mnA = fmaxf(mA[mi], mxA), mnB = fmaxf(mB[mi], mxB);
                float cA = __expf(mA[mi] - mnA), cB = __expf(mB[mi] - mnB);
                float rsA = 0.f, rsB = 0.f;
#pragma unroll
                for (int n = 0; n < 4; n++) {
                    s[mi][n][0] = __expf(s[mi][n][0] - mnA);
                    s[mi][n][1] = __expf(s[mi][n][1] - mnA);
                    s[mi][n][2] = __expf(s[mi][n][2] - mnB);
                    s[mi][n][3] = __expf(s[mi][n][3] - mnB);
                    rsA += s[mi][n][0] + s[mi][n][1];
                    rsB += s[mi][n][2] + s[mi][n][3];
                }
#pragma unroll
                for (int off = 1; off < 4; off <<= 1) {
                    rsA += __shfl_xor_sync(0xffffffffu, rsA, off);
                    rsB += __shfl_xor_sync(0xffffffffu, rsB, off);
                }
                lA[mi] = lA[mi] * cA + rsA;  mA[mi] = mnA;
                lB[mi] = lB[mi] * cB + rsB;  mB[mi] = mnB;
#pragma unroll
                for (int n = 0; n < 16; n++) {
                    o[mi][n][0] *= cA; o[mi][n][1] *= cA;
                    o[mi][n][2] *= cB; o[mi][n][3] *= cB;
                }
#pragma unroll
                for (int j2 = 0; j2 < 2; j2++) {
#pragma unroll
                    for (int hf = 0; hf < 2; hf++) {
                        int j = 2 * j2 + hf;
                        __nv_bfloat16 h0 = __float2bfloat16(s[mi][j][0]);
                        __nv_bfloat16 h1 = __float2bfloat16(s[mi][j][1]);
                        __nv_bfloat16 h2 = __float2bfloat16(s[mi][j][2]);
                        __nv_bfloat16 h3 = __float2bfloat16(s[mi][j][3]);
                        ph[mi][j2][2 * hf]     = pack2(h0, h1);
                        ph[mi][j2][2 * hf + 1] = pack2(h2, h3);
                        pl[mi][j2][2 * hf]     = packf2(s[mi][j][0] - __bfloat162float(h0),
                                                        s[mi][j][1] - __bfloat162float(h1));
                        pl[mi][j2][2 * hf + 1] = packf2(s[mi][j][2] - __bfloat162float(h2),
                                                        s[mi][j][3] - __bfloat162float(h3));
                    }
                }
            }

            // ---- O += P V (3-term split) ----
#pragma unroll
            for (int j2 = 0; j2 < 2; j2++) {
#pragma unroll
                for (int nn = 0; nn < 8; nn++) {
                    uint32_t voff = (uint32_t)((j2 * 16 + v_kr) * ALD + nn * 16 + v_nc) * 2;
                    uint32_t vh01[2], vh23[2], vl01[2], vl23[2];
                    LDSM_X4_T(vh01[0], vh01[1], vh23[0], vh23[1], st + 2 * AKV_BYTES + voff);
                    LDSM_X4_T(vl01[0], vl01[1], vl23[0], vl23[1], st + 3 * AKV_BYTES + voff);
#pragma unroll
                    for (int mi = 0; mi < 2; mi++) {
                        mma_bf16(o[mi][2 * nn],     ph[mi][j2], vh01);
                        mma_bf16(o[mi][2 * nn + 1], ph[mi][j2], vh23);
                        mma_bf16(o[mi][2 * nn],     pl[mi][j2], vh01);
                        mma_bf16(o[mi][2 * nn + 1], pl[mi][j2], vh23);
                        mma_bf16(o[mi][2 * nn],     ph[mi][j2], vl01);
                        mma_bf16(o[mi][2 * nn + 1], ph[mi][j2], vl23);
                    }
                }
            }
        }
        __syncthreads();
    }

    // ---- epilogue: normalize, split to bf16 hi/lo, store ----
#pragma unroll
    for (int mi = 0; mi < 2; mi++) {
        const float iA = 1.f / lA[mi];
        const float iB = 1.f / lB[mi];
        const size_t bA = (rowbase + row0 + mi * 16 + r0l) * (size_t)INNER
                          + h * HEAD_DIM + 2 * (l & 3);
        const size_t bB = bA + 8 * (size_t)INNER;
#pragma unroll
        for (int n = 0; n < 16; n++) {
            float vA0 = o[mi][n][0] * iA, vA1 = o[mi][n][1] * iA;
            float vB0 = o[mi][n][2] * iB, vB1 = o[mi][n][3] * iB;
            __nv_bfloat16 hA0 = __float2bfloat16(vA0), hA1 = __float2bfloat16(vA1);
            __nv_bfloat16 hB0 = __float2bfloat16(vB0), hB1 = __float2bfloat16(vB1);
            *(uint32_t*)(outh + bA + 8 * n) = pack2(hA0, hA1);
            *(uint32_t*)(outh + bB + 8 * n) = pack2(hB0, hB1);
            *(uint32_t*)(outl + bA + 8 * n) = packf2(vA0 - __bfloat162float(hA0),
                                                     vA1 - __bfloat162float(hA1));
            *(uint32_t*)(outl + bB + 8 * n) = packf2(vB0 - __bfloat162float(hB0),
                                                     vB1 - __bfloat162float(hB1));
        }
    }
}

// ---------------------------------------------------------------------------
extern "C" void kernel_launch(void* const* d_in, const int* in_sizes, int n_in,
                              void* d_out, int out_size)
{
    const float* x      = (const float*)d_in[0];
    const float* W_qkv  = (const float*)d_in[1];
    const float* W_proj = (const float*)d_in[2];
    float* out = (float*)d_out;

    __nv_bfloat16 *qkvh, *qkvl, *xh, *xl, *wqh, *wql, *wph, *wpl, *ah, *al;
    float2* rope;
    cudaGetSymbolAddress((void**)&qkvh, g_qkvh);
    cudaGetSymbolAddress((void**)&qkvl, g_qkvl);
    cudaGetSymbolAddress((void**)&xh, g_xh);
    cudaGetSymbolAddress((void**)&xl, g_xl);
    cudaGetSymbolAddress((void**)&wqh, g_wqh);
    cudaGetSymbolAddress((void**)&wql, g_wql);
    cudaGetSymbolAddress((void**)&wph, g_wph);
    cudaGetSymbolAddress((void**)&wpl, g_wpl);
    cudaGetSymbolAddress((void**)&ah, g_ah);
    cudaGetSymbolAddress((void**)&al, g_al);
    cudaGetSymbolAddress((void**)&rope, g_rope);

    cudaFuncSetAttribute(gemm_bf16x3, cudaFuncAttributeMaxDynamicSharedMemorySize,
                         GEMM_SMEM);
    cudaFuncSetAttribute(attn_mma, cudaFuncAttributeMaxDynamicSharedMemorySize,
                         ATTN_SMEM);

    // Prep: splits + rope table
    split_kernel<<<(MTOK * DIM / 4) / 256, 256>>>(x, xh, xl, MTOK * DIM / 4);
    split_kernel<<<(QKV_N * DIM / 4) / 256, 256>>>(W_qkv, wqh, wql, QKV_N * DIM / 4);
    split_kernel<<<(INNER * DIM / 4) / 256, 256>>>(W_proj, wph, wpl, INNER * DIM / 4);
    rope_table_kernel<<<(T_ * 64) / 256, 256>>>(rope);

    // 1) qkv = x @ W_qkv^T with fused RoPE + hi/lo split epilogue
    gemm_bf16x3<<<dim3(QKV_N / GBN, MTOK / GBM), 256, GEMM_SMEM>>>(
        xh, xl, wqh, wql, nullptr, qkvh, qkvl, rope, MTOK, QKV_N, DIM, 1);

    // 2) HMMA causal flash attention v2 (256 q-rows/CTA, 32-row KV tiles)
    attn_mma<<<dim3(T_ / 256, B_ * HEADS), 256, ATTN_SMEM>>>(qkvh, qkvl, ah, al);

    // 3) out = attn @ W_proj^T (fp32 epilogue)
    gemm_bf16x3<<<dim3(INNER / GBN, MTOK / GBM), 256, GEMM_SMEM>>>(
        ah, al, wph, wpl, out, nullptr, nullptr, rope, MTOK, INNER, DIM, 0);
}

// round 12
// speedup vs baseline: 1.0703x; 1.0703x over previous
#include <cuda_runtime.h>
#include <cuda_bf16.h>
#include <math.h>
#include <cstdint>

#define HEADS    16
#define HEAD_DIM 128
#define B_       2
#define T_       2048
#define DIM      2048
#define INNER    (HEADS * HEAD_DIM)   // 2048
#define QKV_N    (3 * INNER)          // 6144
#define MTOK     (B_ * T_)            // 4096

// ---------------------------------------------------------------------------
// Scratch (allocation-free rule: __device__ globals)
// ---------------------------------------------------------------------------
__device__ __nv_bfloat16 g_qkvh[(size_t)MTOK * QKV_N], g_qkvl[(size_t)MTOK * QKV_N];
__device__ __nv_bfloat16 g_xh[(size_t)MTOK * DIM],  g_xl[(size_t)MTOK * DIM];
__device__ __nv_bfloat16 g_wqh[(size_t)QKV_N * DIM], g_wql[(size_t)QKV_N * DIM];
__device__ __nv_bfloat16 g_wph[(size_t)INNER * DIM], g_wpl[(size_t)INNER * DIM];
__device__ __nv_bfloat16 g_ah[(size_t)MTOK * INNER], g_al[(size_t)MTOK * INNER];
__device__ float2 g_rope[(size_t)T_ * 64];           // cos/sin table

// ---------------------------------------------------------------------------
// PTX helpers (baseline ISA only — plain sm_103 target)
// ---------------------------------------------------------------------------
__device__ __forceinline__ uint32_t smem_to_u32(const void* p) {
    uint32_t a;
    asm("{ .reg .u64 t; cvta.to.shared.u64 t, %1; cvt.u32.u64 %0, t; }"
        : "=r"(a) : "l"(p));
    return a;
}
__device__ __forceinline__ void cp_async16(uint32_t dst, const void* src) {
    asm volatile("cp.async.cg.shared.global [%0], [%1], 16;" :: "r"(dst), "l"(src));
}
#define CP_COMMIT() asm volatile("cp.async.commit_group;" ::: "memory")
#define CP_WAIT(n)  asm volatile("cp.async.wait_group %0;" :: "n"(n) : "memory")

#define LDSM_X4(r0, r1, r2, r3, addr) \
    asm volatile("ldmatrix.sync.aligned.m8n8.x4.shared.b16 {%0,%1,%2,%3}, [%4];" \
        : "=r"(r0), "=r"(r1), "=r"(r2), "=r"(r3) : "r"(addr))
#define LDSM_X4_T(r0, r1, r2, r3, addr) \
    asm volatile("ldmatrix.sync.aligned.m8n8.x4.trans.shared.b16 {%0,%1,%2,%3}, [%4];" \
        : "=r"(r0), "=r"(r1), "=r"(r2), "=r"(r3) : "r"(addr))

__device__ __forceinline__ void mma_bf16(float* c, const uint32_t* a, const uint32_t* b)
{
    asm volatile(
        "mma.sync.aligned.m16n8k16.row.col.f32.bf16.bf16.f32 "
        "{%0,%1,%2,%3}, {%4,%5,%6,%7}, {%8,%9}, {%0,%1,%2,%3};"
        : "+f"(c[0]), "+f"(c[1]), "+f"(c[2]), "+f"(c[3])
        : "r"(a[0]), "r"(a[1]), "r"(a[2]), "r"(a[3]), "r"(b[0]), "r"(b[1]));
}

__device__ __forceinline__ float ex2f(float x) {
    float r;
    asm("ex2.approx.f32 %0, %1;" : "=f"(r) : "f"(x));
    return r;
}

__device__ __forceinline__ uint32_t pack2(__nv_bfloat16 a, __nv_bfloat16 b) {
    __nv_bfloat162 t(a, b);
    return *reinterpret_cast<uint32_t*>(&t);
}
__device__ __forceinline__ uint32_t packf2(float lo, float hi) {
    __nv_bfloat162 t = __floats2bfloat162_rn(lo, hi);
    return *reinterpret_cast<uint32_t*>(&t);
}

// ---------------------------------------------------------------------------
// Fused 3-array split: fp32 -> (hi bf16, lo bf16) for x, W_qkv, W_proj
// ---------------------------------------------------------------------------
#define N4_X  (MTOK * DIM / 4)                    // 2097152
#define N4_WQ (QKV_N * DIM / 4)                   // 3145728
#define N4_WP (INNER * DIM / 4)                   // 1048576
#define N4_TOTAL (N4_X + N4_WQ + N4_WP)           // 6291456

__global__ void split3_kernel(const float* __restrict__ x,
                              const float* __restrict__ wq,
                              const float* __restrict__ wp,
                              __nv_bfloat16* __restrict__ xh, __nv_bfloat16* __restrict__ xl,
                              __nv_bfloat16* __restrict__ wqh, __nv_bfloat16* __restrict__ wql,
                              __nv_bfloat16* __restrict__ wph, __nv_bfloat16* __restrict__ wpl)
{
    int i = blockIdx.x * 256 + threadIdx.x;
    const float* src;
    __nv_bfloat16 *hi, *lo;
    int idx;
    if (i < N4_X)            { src = x;  hi = xh;  lo = xl;  idx = i; }
    else if (i < N4_X + N4_WQ) { src = wq; hi = wqh; lo = wql; idx = i - N4_X; }
    else                     { src = wp; hi = wph; lo = wpl; idx = i - N4_X - N4_WQ; }

    float4 v = ((const float4*)src)[idx];
    float f[4] = {v.x, v.y, v.z, v.w};
    __nv_bfloat162 h2[2], l2[2];
#pragma unroll
    for (int j = 0; j < 2; j++) {
        __nv_bfloat16 h0 = __float2bfloat16(f[2 * j]);
        __nv_bfloat16 h1 = __float2bfloat16(f[2 * j + 1]);
        __nv_bfloat16 l0 = __float2bfloat16(f[2 * j] - __bfloat162float(h0));
        __nv_bfloat16 l1 = __float2bfloat16(f[2 * j + 1] - __bfloat162float(h1));
        h2[j] = __nv_bfloat162(h0, h1);
        l2[j] = __nv_bfloat162(l0, l1);
    }
    ((__nv_bfloat162*)hi)[2 * idx]     = h2[0];
    ((__nv_bfloat162*)hi)[2 * idx + 1] = h2[1];
    ((__nv_bfloat162*)lo)[2 * idx]     = l2[0];
    ((__nv_bfloat162*)lo)[2 * idx + 1] = l2[1];
}

// ---------------------------------------------------------------------------
// RoPE cos/sin table init
// ---------------------------------------------------------------------------
__global__ void rope_table_kernel(float2* __restrict__ tab)
{
    int idx = blockIdx.x * 256 + threadIdx.x;   // 0 .. 2048*64-1
    int i = idx & 63;
    int t = idx >> 6;
    float inv = exp2f(-(float)i * 0.20761871929656223f);  // log2(1e4)/64
    float ang = (float)t * inv;
    float sn, cs;
    sincosf(ang, &sn, &cs);
    tab[idx] = make_float2(cs, sn);
}

// ---------------------------------------------------------------------------
// HMMA GEMM (v4 core): C = (Ah+Al) @ (Bh+Bl)^T, 3-term bf16 split.
// Tile 128x128, BK=32, 8 warps (2x4), warp tile 64x32, 2-stage cp.async,
// 2 CTAs/SM, mi pairs (8 indep chains).
// mode 0: fp32 C.  mode 1: fused RoPE + hi/lo split epilogue (vectorized).
// ---------------------------------------------------------------------------
#define GBM 128
#define GBN 128
#define GBK 32
#define LDA 40
#define MAT_BYTES (128 * LDA * 2)           // 10240
#define STAGE_BYTES (4 * MAT_BYTES)         // 40960
#define GEMM_SMEM (2 * STAGE_BYTES)         // 81920 per CTA -> 2 CTAs/SM
#define LDC 132                             // fp32 epilogue staging stride

__device__ __forceinline__ void issue_stage(
    const __nv_bfloat16* __restrict__ Ah, const __nv_bfloat16* __restrict__ Al,
    const __nv_bfloat16* __restrict__ Bh, const __nv_bfloat16* __restrict__ Bl,
    size_t bm, size_t bn, int K, int k0, uint32_t sbase, int tid)
{
#pragma unroll
    for (int i = 0; i < 2; i++) {
        int idx = tid + i * 256;            // 0..511
        int r   = idx >> 2;                 // 0..127
        int c   = (idx & 3) << 3;           // 0,8,16,24
        uint32_t doff = (uint32_t)(r * LDA + c) * 2;
        size_t asrc = (bm + (size_t)r) * K + k0 + c;
        size_t bsrc = (bn + (size_t)r) * K + k0 + c;
        cp_async16(sbase + doff,                 Ah + asrc);
        cp_async16(sbase + MAT_BYTES + doff,     Al + asrc);
        cp_async16(sbase + 2 * MAT_BYTES + doff, Bh + bsrc);
        cp_async16(sbase + 3 * MAT_BYTES + doff, Bl + bsrc);
    }
}

__global__ __launch_bounds__(256, 2)
void gemm_bf16x3(const __nv_bfloat16* __restrict__ Ah, const __nv_bfloat16* __restrict__ Al,
                 const __nv_bfloat16* __restrict__ Bh, const __nv_bfloat16* __restrict__ Bl,
                 float* __restrict__ C,
                 __nv_bfloat16* __restrict__ Oh, __nv_bfloat16* __restrict__ Ol,
                 const float2* __restrict__ rope,
                 int M, int N, int K, int mode)
{
    extern __shared__ char smem[];
    const uint32_t s0 = smem_to_u32(smem);

    const int tid = threadIdx.x;
    const int wid = tid >> 5;
    const int l   = tid & 31;
    const int warp_m = wid & 1;
    const int warp_n = wid >> 1;
    const size_t bm = (size_t)blockIdx.y * GBM;
    const size_t bn = (size_t)blockIdx.x * GBN;

    float acc[4][4][4];
#pragma unroll
    for (int mi = 0; mi < 4; mi++)
#pragma unroll
        for (int ni = 0; ni < 4; ni++)
#pragma unroll
            for (int e = 0; e < 4; e++) acc[mi][ni][e] = 0.f;

    const int S = K / GBK;
    issue_stage(Ah, Al, Bh, Bl, bm, bn, K, 0, s0, tid);
    CP_COMMIT();

    const int a_row = warp_m * 64 + (l & 15);
    const int a_ch  = (l >> 4) << 3;
    const int g     = l >> 3;
    const int b_row = warp_n * 32 + ((g >> 1) << 3) + (l & 7);
    const int b_ch  = (g & 1) << 3;

    for (int s = 0; s < S; s++) {
        if (s + 1 < S) {
            issue_stage(Ah, Al, Bh, Bl, bm, bn, K, (s + 1) * GBK,
                        s0 + ((s + 1) & 1) * STAGE_BYTES, tid);
            CP_COMMIT();
            CP_WAIT(1);
        } else {
            CP_WAIT(0);
        }
        __syncthreads();

        const uint32_t ahB = s0 + (s & 1) * STAGE_BYTES;
        const uint32_t alB = ahB + MAT_BYTES;
        const uint32_t bhB = ahB + 2 * MAT_BYTES;
        const uint32_t blB = ahB + 3 * MAT_BYTES;

#pragma unroll
        for (int ks = 0; ks < 2; ks++) {
            const int kc = ks * 16;
            uint32_t bh[4][2], bl[4][2];
#pragma unroll
            for (int nt = 0; nt < 2; nt++) {
                uint32_t off = (uint32_t)((b_row + nt * 16) * LDA + kc + b_ch) * 2;
                LDSM_X4(bh[2 * nt][0], bh[2 * nt][1], bh[2 * nt + 1][0], bh[2 * nt + 1][1], bhB + off);
                LDSM_X4(bl[2 * nt][0], bl[2 * nt][1], bl[2 * nt + 1][0], bl[2 * nt + 1][1], blB + off);
            }
#pragma unroll
            for (int mp = 0; mp < 2; mp++) {
                const int mi0 = 2 * mp, mi1 = 2 * mp + 1;
                uint32_t ah0[4], al0[4], ah1[4], al1[4];
                uint32_t off0 = (uint32_t)((a_row + mi0 * 16) * LDA + kc + a_ch) * 2;
                uint32_t off1 = (uint32_t)((a_row + mi1 * 16) * LDA + kc + a_ch) * 2;
                LDSM_X4(ah0[0], ah0[1], ah0[2], ah0[3], ahB + off0);
                LDSM_X4(ah1[0], ah1[1], ah1[2], ah1[3], ahB + off1);
                LDSM_X4(al0[0], al0[1], al0[2], al0[3], alB + off0);
                LDSM_X4(al1[0], al1[1], al1[2], al1[3], alB + off1);
#pragma unroll
                for (int ni = 0; ni < 4; ni++) {
                    mma_bf16(acc[mi0][ni], ah0, bh[ni]);
                    mma_bf16(acc[mi1][ni], ah1, bh[ni]);
                }
#pragma unroll
                for (int ni = 0; ni < 4; ni++) {
                    mma_bf16(acc[mi0][ni], al0, bh[ni]);
                    mma_bf16(acc[mi1][ni], al1, bh[ni]);
                }
#pragma unroll
                for (int ni = 0; ni < 4; ni++) {
                    mma_bf16(acc[mi0][ni], ah0, bl[ni]);
                    mma_bf16(acc[mi1][ni], ah1, bl[ni]);
                }
            }
        }
        __syncthreads();
    }

    if (mode == 0) {
        const size_t row0 = bm + warp_m * 64 + (l >> 2);
        const int    col0 = (int)bn + warp_n * 32 + 2 * (l & 3);
#pragma unroll
        for (int mi = 0; mi < 4; mi++) {
#pragma unroll
            for (int ni = 0; ni < 4; ni++) {
                float* p0 = C + (row0 + mi * 16) * N + col0 + ni * 8;
                float* p1 = p0 + 8 * (size_t)N;
                *(float2*)p0 = make_float2(acc[mi][ni][0], acc[mi][ni][1]);
                *(float2*)p1 = make_float2(acc[mi][ni][2], acc[mi][ni][3]);
            }
        }
    } else {
        // fused RoPE + hi/lo split epilogue; tile = one head.
        float* sC = (float*)smem;           // 128 x LDC fp32
        const int r0 = warp_m * 64 + (l >> 2);
        const int c0 = warp_n * 32 + 2 * (l & 3);
#pragma unroll
        for (int mi = 0; mi < 4; mi++) {
#pragma unroll
            for (int ni = 0; ni < 4; ni++) {
                int rr = r0 + mi * 16, cc = c0 + ni * 8;
                sC[rr * LDC + cc]           = acc[mi][ni][0];
                sC[rr * LDC + cc + 1]       = acc[mi][ni][1];
                sC[(rr + 8) * LDC + cc]     = acc[mi][ni][2];
                sC[(rr + 8) * LDC + cc + 1] = acc[mi][ni][3];
            }
        }
        __syncthreads();

        const int sec = (int)(bn / INNER);  // 0=q, 1=k, 2=v
#pragma unroll
        for (int j = 0; j < 16; j++) {
            int p = tid + j * 256;          // 0..4095 double-pairs
            int r = p >> 5;                 // 0..127
            int c = (p & 31) << 1;          // 0,2,...,62
            float x1a = sC[r * LDC + c];
            float x1b = sC[r * LDC + c + 1];
            float x2a = sC[r * LDC + c + 64];
            float x2b = sC[r * LDC + c + 65];
            float y1a = x1a, y1b = x1b, y2a = x2a, y2b = x2b;
            if (sec < 2) {
                int t = (int)((bm + r) & (T_ - 1));
                float2 ca = rope[t * 64 + c];
                float2 cb = rope[t * 64 + c + 1];
                y1a = x1a * ca.x - x2a * ca.y;
                y2a = x2a * ca.x + x1a * ca.y;
                y1b = x1b * cb.x - x2b * cb.y;
                y2b = x2b * cb.x + x1b * cb.y;
            }
            __nv_bfloat16 h1a = __float2bfloat16(y1a), h1b = __float2bfloat16(y1b);
            __nv_bfloat16 h2a = __float2bfloat16(y2a), h2b = __float2bfloat16(y2b);
            size_t o = (bm + r) * (size_t)QKV_N + bn + c;
            *(uint32_t*)(Oh + o)      = pack2(h1a, h1b);
            *(uint32_t*)(Oh + o + 64) = pack2(h2a, h2b);
            *(uint32_t*)(Ol + o)      = packf2(y1a - __bfloat162float(h1a),
                                               y1b - __bfloat162float(h1b));
            *(uint32_t*)(Ol + o + 64) = packf2(y2a - __bfloat162float(h2a),
                                               y2b - __bfloat162float(h2b));
        }
    }
}

// ---------------------------------------------------------------------------
// HMMA causal flash attention (round-10 design): warp = 16 q-rows, KV = 64,
// Q fragments resident in regs. Softmax in log2 domain (scale*log2e folded).
// ---------------------------------------------------------------------------
#define ALD 136
#define AQ_BYTES   (128 * ALD * 2)
#define AKV_BYTES  (64 * ALD * 2)
#define AKV_STAGE  (4 * AKV_BYTES)
#define ATTN_SMEM  (2 * AQ_BYTES + 2 * AKV_STAGE)

__global__ __launch_bounds__(256, 1)
void attn_mma(const __nv_bfloat16* __restrict__ QKVh,
              const __nv_bfloat16* __restrict__ QKVl,
              __nv_bfloat16* __restrict__ outh,
              __nv_bfloat16* __restrict__ outl)
{
    extern __shared__ char smem[];
    const uint32_t s0  = smem_to_u32(smem);
    const uint32_t qhB = s0;
    const uint32_t qlB = s0 + AQ_BYTES;
    const uint32_t kvB = s0 + 2 * AQ_BYTES;

    const int tid = threadIdx.x;
    const int wid = tid >> 5;
    const int l   = tid & 31;
    const int qb  = (int)gridDim.x - 1 - (int)blockIdx.x;
    const int b   = (int)blockIdx.y >> 4;
    const int h   = (int)blockIdx.y & 15;
    const int q0  = qb * 128;
    const size_t rowbase = (size_t)b * T_;
    // scale * log2(e): softmax computed in base-2 domain
    const float kscale = 0.08838834764831843f * 1.44269504088896341f;

#pragma unroll
    for (int it = 0; it < 16; it++) {
        int idx = tid + it * 256;
        int mat = idx >> 11;
        int r   = (idx >> 4) & 127;
        int c   = idx & 15;
        const __nv_bfloat16* src = (mat ? QKVl : QKVh) +
            (rowbase + q0 + r) * QKV_N + h * HEAD_DIM + c * 8;
        cp_async16((mat ? qlB : qhB) + (uint32_t)(r * ALD + c * 8) * 2, src);
    }

    auto issue_kv = [&](int kv0, int buf) {
        uint32_t base = kvB + (uint32_t)buf * AKV_STAGE;
#pragma unroll
        for (int it = 0; it < 16; it++) {
            int idx = tid + it * 256;
            int m   = idx >> 10;
            int r   = (idx >> 4) & 63;
            int c   = idx & 15;
            const __nv_bfloat16* p = (m & 1) ? QKVl : QKVh;
            int sect = (m >> 1) ? 2 * INNER : INNER;
            const __nv_bfloat16* src = p +
                (rowbase + kv0 + r) * QKV_N + sect + h * HEAD_DIM + c * 8;
            cp_async16(base + (uint32_t)m * AKV_BYTES + (uint32_t)(r * ALD + c * 8) * 2, src);
        }
    };

    const int a_row  = wid * 16 + (l & 15);
    const int a_ch   = (l >> 4) << 3;
    const int g      = l >> 3;
    const int bn_row = ((g >> 1) << 3) + (l & 7);
    const int b_ch   = (g & 1) << 3;
    const int v_kr   = (((l >> 3) & 1) << 3) + (l & 7);
    const int v_nc   = (l >> 4) << 3;

    float o[16][4];
#pragma unroll
    for (int n = 0; n < 16; n++)
#pragma unroll
        for (int e = 0; e < 4; e++) o[n][e] = 0.f;
    float mA = -INFINITY, mB = -INFINITY, lA = 0.f, lB = 0.f;

    // Q fragments resident in registers (loaded once at t==0)
    uint32_t qA[8][4], qL[8][4];

    const int ntiles = 2 * qb + 2;
    issue_kv(0, 0);
    CP_COMMIT();

    const int row0 = q0 + wid * 16;
    const int r0l  = l >> 2;
    const int rowA = row0 + r0l;
    const int rowB = rowA + 8;

    for (int t = 0; t < ntiles; t++) {
        if (t + 1 < ntiles) {
            issue_kv((t + 1) * 64, (t + 1) & 1);
            CP_COMMIT();
            CP_WAIT(1);
        } else {
            CP_WAIT(0);
        }
        __syncthreads();

        if (t == 0) {
#pragma unroll
            for (int kk = 0; kk < 8; kk++) {
                uint32_t qoff = (uint32_t)(a_row * ALD + kk * 16 + a_ch) * 2;
                LDSM_X4(qA[kk][0], qA[kk][1], qA[kk][2], qA[kk][3], qhB + qoff);
                LDSM_X4(qL[kk][0], qL[kk][1], qL[kk][2], qL[kk][3], qlB + qoff);
            }
        }

        const int kv0 = t * 64;
        const uint32_t st = kvB + (uint32_t)(t & 1) * AKV_STAGE;

        if (kv0 <= row0 + 15) {
            float s[8][4];
#pragma unroll
            for (int n = 0; n < 8; n++)
#pragma unroll
                for (int e = 0; e < 4; e++) s[n][e] = 0.f;

#pragma unroll
            for (int kk = 0; kk < 8; kk++) {
                const int kc = kk * 16;
                uint32_t kh[8][2], kl[8][2];
#pragma unroll
                for (int nt = 0; nt < 4; nt++) {
                    uint32_t koff = (uint32_t)((nt * 16 + bn_row) * ALD + kc + b_ch) * 2;
                    LDSM_X4(kh[2 * nt][0], kh[2 * nt][1], kh[2 * nt + 1][0], kh[2 * nt + 1][1],
                            st + koff);
                    LDSM_X4(kl[2 * nt][0], kl[2 * nt][1], kl[2 * nt + 1][0], kl[2 * nt + 1][1],
                            st + AKV_BYTES + koff);
                }
#pragma unroll
                for (int n = 0; n < 8; n++) {
                    mma_bf16(s[n], qA[kk], kh[n]);
                    mma_bf16(s[n], qL[kk], kh[n]);
                    mma_bf16(s[n], qA[kk], kl[n]);
                }
            }

            // scale into log2 domain
#pragma unroll
            for (int n = 0; n < 8; n++)
#pragma unroll
                for (int e = 0; e < 4; e++) s[n][e] *= kscale;

            if (kv0 + 63 > row0) {
                const int cb = kv0 + 2 * (l & 3);
#pragma unroll
                for (int n = 0; n < 8; n++) {
                    int c0 = cb + 8 * n;
                    if (c0     > rowA) s[n][0] = -INFINITY;
                    if (c0 + 1 > rowA) s[n][1] = -INFINITY;
                    if (c0     > rowB) s[n][2] = -INFINITY;
                    if (c0 + 1 > rowB) s[n][3] = -INFINITY;
                }
            }

            float mxA = -INFINITY, mxB = -INFINITY;
#pragma unroll
            for (int n = 0; n < 8; n++) {
                mxA = fmaxf(mxA, fmaxf(s[n][0], s[n][1]));
                mxB = fmaxf(mxB, fmaxf(s[n][2], s[n][3]));
            }
#pragma unroll
            for (int off = 1; off < 4; off <<= 1) {
                mxA = fmaxf(mxA, __shfl_xor_sync(0xffffffffu, mxA, off));
                mxB = fmaxf(mxB, __shfl_xor_sync(0xffffffffu, mxB, off));
            }
            float mnA = fmaxf(mA, mxA), mnB = fmaxf(mB, mxB);
            float cA = ex2f(mA - mnA), cB = ex2f(mB - mnB);
            float rsA = 0.f, rsB = 0.f;
#pragma unroll
            for (int n = 0; n < 8; n++) {
                s[n][0] = ex2f(s[n][0] - mnA);
                s[n][1] = ex2f(s[n][1] - mnA);
                s[n][2] = ex2f(s[n][2] - mnB);
                s[n][3] = ex2f(s[n][3] - mnB);
                rsA += s[n][0] + s[n][1];
                rsB += s[n][2] + s[n][3];
            }
#pragma unroll
            for (int off = 1; off < 4; off <<= 1) {
                rsA += __shfl_xor_sync(0xffffffffu, rsA, off);
                rsB += __shfl_xor_sync(0xffffffffu, rsB, off);
            }
            lA = lA * cA + rsA;  mA = mnA;
            lB = lB * cB + rsB;  mB = mnB;
#pragma unroll
            for (int n = 0; n < 16; n++) {
                o[n][0] *= cA; o[n][1] *= cA;
                o[n][2] *= cB; o[n][3] *= cB;
            }

            uint32_t ph[4][4], pl[4][4];
#pragma unroll
            for (int j2 = 0; j2 < 4; j2++) {
#pragma unroll
                for (int hf = 0; hf < 2; hf++) {
                    int j = 2 * j2 + hf;
                    __nv_bfloat16 h0 = __float2bfloat16(s[j][0]);
                    __nv_bfloat16 h1 = __float2bfloat16(s[j][1]);
                    __nv_bfloat16 h2 = __float2bfloat16(s[j][2]);
                    __nv_bfloat16 h3 = __float2bfloat16(s[j][3]);
                    ph[j2][2 * hf]     = pack2(h0, h1);
                    ph[j2][2 * hf + 1] = pack2(h2, h3);
                    pl[j2][2 * hf]     = packf2(s[j][0] - __bfloat162float(h0),
                                                s[j][1] - __bfloat162float(h1));
                    pl[j2][2 * hf + 1] = packf2(s[j][2] - __bfloat162float(h2),
                                                s[j][3] - __bfloat162float(h3));
                }
            }

#pragma unroll
            for (int j2 = 0; j2 < 4; j2++) {
#pragma unroll
                for (int nn = 0; nn < 8; nn++) {
                    uint32_t voff = (uint32_t)((j2 * 16 + v_kr) * ALD + nn * 16 + v_nc) * 2;
                    uint32_t vh01[2], vh23[2], vl01[2], vl23[2];
                    LDSM_X4_T(vh01[0], vh01[1], vh23[0], vh23[1], st + 2 * AKV_BYTES + voff);
                    LDSM_X4_T(vl01[0], vl01[1], vl23[0], vl23[1], st + 3 * AKV_BYTES + voff);
                    mma_bf16(o[2 * nn],     ph[j2], vh01);
                    mma_bf16(o[2 * nn + 1], ph[j2], vh23);
                    mma_bf16(o[2 * nn],     pl[j2], vh01);
                    mma_bf16(o[2 * nn + 1], pl[j2], vh23);
                    mma_bf16(o[2 * nn],     ph[j2], vl01);
                    mma_bf16(o[2 * nn + 1], ph[j2], vl23);
                }
            }
        }
        __syncthreads();
    }

    const float iA = 1.f / lA;
    const float iB = 1.f / lB;
    const size_t bA = (rowbase + rowA) * (size_t)INNER + h * HEAD_DIM + 2 * (l & 3);
    const size_t bB = bA + 8 * (size_t)INNER;
#pragma unroll
    for (int n = 0; n < 16; n++) {
        float vA0 = o[n][0] * iA, vA1 = o[n][1] * iA;
        float vB0 = o[n][2] * iB, vB1 = o[n][3] * iB;
        __nv_bfloat16 hA0 = __float2bfloat16(vA0), hA1 = __float2bfloat16(vA1);
        __nv_bfloat16 hB0 = __float2bfloat16(vB0), hB1 = __float2bfloat16(vB1);
        *(uint32_t*)(outh + bA + 8 * n) = pack2(hA0, hA1);
        *(uint32_t*)(outh + bB + 8 * n) = pack2(hB0, hB1);
        *(uint32_t*)(outl + bA + 8 * n) = packf2(vA0 - __bfloat162float(hA0),
                                                 vA1 - __bfloat162float(hA1));
        *(uint32_t*)(outl + bB + 8 * n) = packf2(vB0 - __bfloat162float(hB0),
                                                 vB1 - __bfloat162float(hB1));
    }
}

// ---------------------------------------------------------------------------
extern "C" void kernel_launch(void* const* d_in, const int* in_sizes, int n_in,
                              void* d_out, int out_size)
{
    const float* x      = (const float*)d_in[0];
    const float* W_qkv  = (const float*)d_in[1];
    const float* W_proj = (const float*)d_in[2];
    float* out = (float*)d_out;

    __nv_bfloat16 *qkvh, *qkvl, *xh, *xl, *wqh, *wql, *wph, *wpl, *ah, *al;
    float2* rope;
    cudaGetSymbolAddress((void**)&qkvh, g_qkvh);
    cudaGetSymbolAddress((void**)&qkvl, g_qkvl);
    cudaGetSymbolAddress((void**)&xh, g_xh);
    cudaGetSymbolAddress((void**)&xl, g_xl);
    cudaGetSymbolAddress((void**)&wqh, g_wqh);
    cudaGetSymbolAddress((void**)&wql, g_wql);
    cudaGetSymbolAddress((void**)&wph, g_wph);
    cudaGetSymbolAddress((void**)&wpl, g_wpl);
    cudaGetSymbolAddress((void**)&ah, g_ah);
    cudaGetSymbolAddress((void**)&al, g_al);
    cudaGetSymbolAddress((void**)&rope, g_rope);

    cudaFuncSetAttribute(gemm_bf16x3, cudaFuncAttributeMaxDynamicSharedMemorySize,
                         GEMM_SMEM);
    cudaFuncSetAttribute(attn_mma, cudaFuncAttributeMaxDynamicSharedMemorySize,
                         ATTN_SMEM);

    // Prep: fused splits (one launch) + rope table
    split3_kernel<<<N4_TOTAL / 256, 256>>>(x, W_qkv, W_proj,
                                           xh, xl, wqh, wql, wph, wpl);
    rope_table_kernel<<<(T_ * 64) / 256, 256>>>(rope);

    // 1) qkv = x @ W_qkv^T with fused RoPE + hi/lo split epilogue
    gemm_bf16x3<<<dim3(QKV_N / GBN, MTOK / GBM), 256, GEMM_SMEM>>>(
        xh, xl, wqh, wql, nullptr, qkvh, qkvl, rope, MTOK, QKV_N, DIM, 1);

    // 2) HMMA causal flash attention (round-10 design + log2-domain softmax)
    attn_mma<<<dim3(T_ / 128, B_ * HEADS), 256, ATTN_SMEM>>>(qkvh, qkvl, ah, al);

    // 3) out = attn @ W_proj^T (fp32 epilogue)
    gemm_bf16x3<<<dim3(INNER / GBN, MTOK / GBM), 256, GEMM_SMEM>>>(
        ah, al, wph, wpl, out, nullptr, nullptr, rope, MTOK, INNER, DIM, 0);
}